// round 13
// baseline (speedup 1.0000x reference)
#include <cuda_runtime.h>
#include <cuda_fp16.h>
#include <cstdint>
#include <math.h>

// SelfAttention B=8, C=64, N=4096 fp32. v8b (v8 with K A-block offset fix):
//  fp16 m16n8k16 + ldmatrix, pre-converted fp16 globals (K pre-scaled by
//  0.125*log2e), ex2.f16x2 softmax, ones-column-MMA rowsum, 32 n-rows/warp,
//  TWO independent 128-thread CTAs per SM (independent barriers/pipelines).
//  FIX vs v8: K A-fragment block stride is 16 rows = nb*32 BYTES (was nb*64,
//  which read wrong rows + uninitialized row padding -> NaN).

#define NSEQ 4096
#define CD   64
#define TOT  (8 * CD * NSEQ)

#define KSB  272               // K row stride bytes (128 n * 2B + 16)
#define STR  272               // Q/V row stride bytes (128 m * 2B + 16)
#define OFF_KS 0               // K [c=64][n=128] fp16, 17408 B
#define STG0   17408           // 2 stages, each Q(17408)+V(17408)
#define STGSZ  34816
#define STGV   17408
#define SMEM_TOTAL 87040       // x2 CTAs = 174080 <= 228KB
#define OSTB   528             // epilogue fp32 O staging stride (offset 0)

#define ONES2 0x3C003C00u      // f16x2 {1.0, 1.0}

__device__ __align__(16) __half gK[TOT];
__device__ __align__(16) __half gQ[TOT];
__device__ __align__(16) __half gV[TOT];

static __device__ __forceinline__ uint32_t smem_u32(const void* p) {
    uint32_t a;
    asm("{ .reg .u64 t; cvta.to.shared.u64 t, %1; cvt.u32.u64 %0, t; }" : "=r"(a) : "l"(p));
    return a;
}
static __device__ __forceinline__ uint32_t pkh2(float lo, float hi) {
    uint32_t d;
    asm("cvt.rn.f16x2.f32 %0, %1, %2;" : "=r"(d) : "f"(hi), "f"(lo));
    return d;
}
static __device__ __forceinline__ uint32_t ex2h2(uint32_t x) {
    uint32_t d;
    asm("ex2.approx.f16x2 %0, %1;" : "=r"(d) : "r"(x));
    return d;
}

#define CP16(dst, src) asm volatile("cp.async.cg.shared.global [%0], [%1], 16;" :: "r"(dst), "l"(src) : "memory")
#define CP_COMMIT()    asm volatile("cp.async.commit_group;" ::: "memory")
#define CP_WAIT(n)     asm volatile("cp.async.wait_group %0;" :: "n"(n) : "memory")

#define LDSM4(r0,r1,r2,r3,a) \
    asm volatile("ldmatrix.sync.aligned.m8n8.x4.shared.b16 {%0,%1,%2,%3}, [%4];" \
        : "=r"(r0),"=r"(r1),"=r"(r2),"=r"(r3) : "r"(a))
#define LDSM4T(r0,r1,r2,r3,a) \
    asm volatile("ldmatrix.sync.aligned.m8n8.x4.trans.shared.b16 {%0,%1,%2,%3}, [%4];" \
        : "=r"(r0),"=r"(r1),"=r"(r2),"=r"(r3) : "r"(a))

#define MMA16(d, a0, a1, a2, a3, b0, b1)                                         \
    asm volatile("mma.sync.aligned.m16n8k16.row.col.f32.f16.f16.f32 "            \
        "{%0,%1,%2,%3}, {%4,%5,%6,%7}, {%8,%9}, {%0,%1,%2,%3};"                  \
        : "+f"((d)[0]), "+f"((d)[1]), "+f"((d)[2]), "+f"((d)[3])                 \
        : "r"(a0), "r"(a1), "r"(a2), "r"(a3), "r"(b0), "r"(b1))

// ---- kernel 1: fp32 -> fp16 (K pre-scaled by 0.125*log2 e) ----
__global__ __launch_bounds__(256)
void cvt_to_f16(const float* __restrict__ K, const float* __restrict__ Q,
                const float* __restrict__ V)
{
    const int i = (blockIdx.x * 256 + threadIdx.x) * 8;
    const float sc = (blockIdx.y == 0) ? 0.18033688011112042f : 1.0f;
    const float* src = (blockIdx.y == 0) ? K : (blockIdx.y == 1) ? Q : V;
    __half* dst = (blockIdx.y == 0) ? gK : (blockIdx.y == 1) ? gQ : gV;
    float4 a = *(const float4*)(src + i);
    float4 b = *(const float4*)(src + i + 4);
    *(uint4*)(dst + i) = make_uint4(pkh2(a.x * sc, a.y * sc), pkh2(a.z * sc, a.w * sc),
                                    pkh2(b.x * sc, b.y * sc), pkh2(b.z * sc, b.w * sc));
}

// ---- kernel 2: attention, 128-thread CTA, 2 CTAs/SM ----
__global__ __launch_bounds__(128, 2)
void attn_mma_v8(float* __restrict__ Out)
{
    extern __shared__ char smem[];
    const uint32_t sb = smem_u32(smem);
    const int tid  = threadIdx.x;
    const int wid  = tid >> 5, lane = tid & 31;
    const int g    = lane >> 2, tig = lane & 3;
    const int nw0  = wid * 32;                  // warp's 32-row block (4 warps x 32 = 128)
    const int b    = blockIdx.y, n0 = blockIdx.x * 128;
    const size_t base = (size_t)b * CD * NSEQ;
    const __half* kh = gK + base;
    const __half* qh = gQ + base;
    const __half* vh = gV + base;

    const int cc = tid >> 4, jc = tid & 15;     // loader: 8 c-rows/pass, 16 chunks/row

    // ---- prologue: K tile [c=64][n=128] + tile 0 Q/V (one cp group) ----
    #pragma unroll
    for (int i = 0; i < 8; ++i) {
        int c = cc + i * 8;
        CP16(sb + OFF_KS + c * KSB + jc * 16, kh + (size_t)c * NSEQ + n0 + jc * 8);
        CP16(sb + STG0 + c * STR + jc * 16, qh + (size_t)c * NSEQ + jc * 8);
        CP16(sb + STG0 + STGV + c * STR + jc * 16, vh + (size_t)c * NSEQ + jc * 8);
    }
    CP_COMMIT();

    float o[2][8][4];                // O: [nblk][ct][frag]
    float ors[2][4];                 // rowsum via ones-MMA
    #pragma unroll
    for (int nb = 0; nb < 2; ++nb) {
        #pragma unroll
        for (int e = 0; e < 4; ++e) ors[nb][e] = 0.f;
        #pragma unroll
        for (int ct = 0; ct < 8; ++ct)
            #pragma unroll
            for (int e = 0; e < 4; ++e) o[nb][ct][e] = 0.f;
    }

    const uint32_t kaddr = sb + OFF_KS + ((lane & 7) + ((lane & 16) ? 8 : 0)) * KSB
                         + (nw0 + ((lane & 8) ? 8 : 0)) * 2;
    const uint32_t qbase = ((lane & 7) + ((lane & 8) ? 8 : 0)) * STR
                         + ((lane & 16) ? 16 : 0);
    const uint32_t vbase = ((lane & 7) + ((lane & 16) ? 8 : 0)) * STR
                         + ((lane & 8) ? 16 : 0);

    CP_WAIT(0);
    __syncthreads();

    // K A-fragments: [nblk][kk][4], constant across all tiles (32 regs)
    // A blocks at n = nw0 and nw0+16  ->  byte offset nb * 32  (FIX)
    uint32_t ak[2][4][4];
    #pragma unroll
    for (int nb = 0; nb < 2; ++nb)
        #pragma unroll
        for (int kk = 0; kk < 4; ++kk)
            LDSM4T(ak[nb][kk][0], ak[nb][kk][1], ak[nb][kk][2], ak[nb][kk][3],
                   kaddr + nb * 32 + kk * 16 * KSB);

    for (int t = 0; t < 32; ++t) {
        const uint32_t stg = sb + STG0 + (uint32_t)(t & 1) * STGSZ;
        const uint32_t qs = stg, vs = stg + STGV;

        if (t > 0) { CP_WAIT(0); __syncthreads(); }   // tile t arrived; other buf free

        if (t + 1 < 32) {            // prefetch tile t+1 into the other stage
            const uint32_t so = sb + STG0 + (uint32_t)((t + 1) & 1) * STGSZ;
            const __half* qsrc = qh + (size_t)(t + 1) * 128;
            const __half* vsrc = vh + (size_t)(t + 1) * 128;
            #pragma unroll
            for (int i = 0; i < 8; ++i) {
                int c = cc + i * 8;
                CP16(so + c * STR + jc * 16, qsrc + (size_t)c * NSEQ + jc * 8);
                CP16(so + STGV + c * STR + jc * 16, vsrc + (size_t)c * NSEQ + jc * 8);
            }
            CP_COMMIT();
        }

        #pragma unroll
        for (int h = 0; h < 2; ++h) {
            const uint32_t hoff = h * 128;

            // ---- GEMM1: S[32n][64m] = (c*K)^T x Q ----
            float s[2][8][4];
            #pragma unroll
            for (int nb = 0; nb < 2; ++nb)
                #pragma unroll
                for (int mt = 0; mt < 8; ++mt)
                    #pragma unroll
                    for (int e = 0; e < 4; ++e) s[nb][mt][e] = 0.f;

            #pragma unroll
            for (int mp = 0; mp < 4; ++mp)
                #pragma unroll
                for (int kk = 0; kk < 4; ++kk) {
                    uint32_t b0, b1, b2, b3;
                    LDSM4T(b0, b1, b2, b3, qs + qbase + kk * 16 * STR + hoff + mp * 32);
                    #pragma unroll
                    for (int nb = 0; nb < 2; ++nb) {
                        MMA16(s[nb][2 * mp],     ak[nb][kk][0], ak[nb][kk][1], ak[nb][kk][2], ak[nb][kk][3], b0, b1);
                        MMA16(s[nb][2 * mp + 1], ak[nb][kk][0], ak[nb][kk][1], ak[nb][kk][2], ak[nb][kk][3], b2, b3);
                    }
                }

            // ---- P = 2^S (pkh2 + ex2.f16x2); O += P x V^T; rowsum += P x 1 ----
            #pragma unroll
            for (int kk = 0; kk < 4; ++kk) {
                uint32_t a[2][4];
                #pragma unroll
                for (int nb = 0; nb < 2; ++nb) {
                    a[nb][0] = ex2h2(pkh2(s[nb][2 * kk][0],     s[nb][2 * kk][1]));
                    a[nb][1] = ex2h2(pkh2(s[nb][2 * kk][2],     s[nb][2 * kk][3]));
                    a[nb][2] = ex2h2(pkh2(s[nb][2 * kk + 1][0], s[nb][2 * kk + 1][1]));
                    a[nb][3] = ex2h2(pkh2(s[nb][2 * kk + 1][2], s[nb][2 * kk + 1][3]));
                    MMA16(ors[nb], a[nb][0], a[nb][1], a[nb][2], a[nb][3], ONES2, ONES2);
                }
                #pragma unroll
                for (int ct = 0; ct < 4; ++ct) {
                    uint32_t b0, b1, b2, b3;
                    LDSM4(b0, b1, b2, b3, vs + vbase + ct * 16 * STR + hoff + kk * 32);
                    #pragma unroll
                    for (int nb = 0; nb < 2; ++nb) {
                        MMA16(o[nb][2 * ct],     a[nb][0], a[nb][1], a[nb][2], a[nb][3], b0, b1);
                        MMA16(o[nb][2 * ct + 1], a[nb][0], a[nb][1], a[nb][2], a[nb][3], b2, b3);
                    }
                }
            }
        }
    }

    // per-lane row sums: ors[nb][0] = row nw0+nb*16+g, ors[nb][2] = +8
    float inv[2][2];
    #pragma unroll
    for (int nb = 0; nb < 2; ++nb) {
        inv[nb][0] = 1.f / ors[nb][0];
        inv[nb][1] = 1.f / ors[nb][2];
    }

    __syncthreads();   // tile smem dead -> O staging [c=64][n=128] stride OSTB

    #pragma unroll
    for (int nb = 0; nb < 2; ++nb)
        #pragma unroll
        for (int ct = 0; ct < 8; ++ct)
            #pragma unroll
            for (int e = 0; e < 4; ++e) {
                int c = 8 * ct + 2 * tig + (e & 1);
                int n = nw0 + nb * 16 + g + 8 * (e >> 1);
                *(float*)(smem + c * OSTB + n * 4) = o[nb][ct][e] * inv[nb][e >> 1];
            }
    __syncthreads();

    // coalesced vectorized store: 64 c-rows x 32 float4
    #pragma unroll
    for (int i = 0; i < 16; ++i) {
        int flat = i * 128 + tid;
        int c = flat >> 5, nq = flat & 31;
        float4 v = *(const float4*)(smem + c * OSTB + nq * 16);
        *(float4*)(Out + base + (size_t)c * NSEQ + n0 + nq * 4) = v;
    }
}

extern "C" void kernel_launch(void* const* d_in, const int* in_sizes, int n_in,
                              void* d_out, int out_size)
{
    const float* k = (const float*)d_in[0];
    const float* q = (const float*)d_in[1];
    const float* v = (const float*)d_in[2];
    float* out = (float*)d_out;

    dim3 gcvt(TOT / (256 * 8), 3);
    cvt_to_f16<<<gcvt, 256>>>(k, q, v);

    cudaFuncSetAttribute(attn_mma_v8, cudaFuncAttributeMaxDynamicSharedMemorySize, SMEM_TOTAL);
    dim3 grid(NSEQ / 128, 8);          // 32 x 8 = 256 CTAs, 2 per SM
    attn_mma_v8<<<grid, 128, SMEM_TOTAL>>>(out);
}